// round 9
// baseline (speedup 1.0000x reference)
#include <cuda_runtime.h>
#include <cuda_bf16.h>

// ---------------------------------------------------------------------------
// Separable RBF network (centers = 20x5x20 meshgrid, uniform beta):
//   exp(-beta|x-c|^2) = u_i(x0) * v_j(x1) * w_k(x2)
//   out = ( sum_ijk W[i,j,k] u_i v_j w_k ) / ( (sum u)(sum v)(sum w) )
// ONE point per thread, f32x2 lanes pack two adjacent k-indices; W loaded
// from smem as ulonglong2 (LDS.128 -> two 64-bit fma2 operands directly,
// all lanes same address = pure broadcast). 131072 threads -> ~28 warps/SM
// at ~64 regs: latency hidden by occupancy instead of per-thread ILP.
// Grid coords / beta / W all read from the input arrays at runtime.
// ---------------------------------------------------------------------------

#define LOG2E 1.4426950408889634f
#define NI 20
#define NJ 5
#define NK 20
#define NC (NI*NJ*NK)
#define TPB 128

typedef unsigned long long u64;

__device__ __forceinline__ u64 pk2(float lo, float hi) {
    u64 r; asm("mov.b64 %0, {%1, %2};" : "=l"(r) : "f"(lo), "f"(hi)); return r;
}
__device__ __forceinline__ void upk2(u64 v, float &lo, float &hi) {
    asm("mov.b64 {%0, %1}, %2;" : "=f"(lo), "=f"(hi) : "l"(v));
}
__device__ __forceinline__ u64 fma2(u64 a, u64 b, u64 c) {
    u64 d; asm("fma.rn.f32x2 %0, %1, %2, %3;" : "=l"(d) : "l"(a), "l"(b), "l"(c)); return d;
}
__device__ __forceinline__ u64 add2(u64 a, u64 b) {
    u64 d; asm("add.rn.f32x2 %0, %1, %2;" : "=l"(d) : "l"(a), "l"(b)); return d;
}
__device__ __forceinline__ float ex2f(float x) {
    float r; asm("ex2.approx.ftz.f32 %0, %1;" : "=f"(r) : "f"(x)); return r;
}

__global__ __launch_bounds__(TPB)
void rbf_sep_kernel(const float* __restrict__ x,
                    const float* __restrict__ centers,
                    const float* __restrict__ beta,
                    const float* __restrict__ lin_w,
                    float* __restrict__ out, int N) {
    __shared__ __align__(16) float sW[NC];     // raw weights, 8 KB
    __shared__ float sg1[NI], sg2[NJ], sg3[NK];

    for (int c = threadIdx.x; c < NC; c += TPB) sW[c] = lin_w[c];
    if (threadIdx.x < NI) sg1[threadIdx.x] = centers[3 * (threadIdx.x * (NJ * NK)) + 0];
    if (threadIdx.x < NJ) sg2[threadIdx.x] = centers[3 * (threadIdx.x * NK) + 1];
    if (threadIdx.x < NK) sg3[threadIdx.x] = centers[3 * threadIdx.x + 2];
    __syncthreads();

    int t = blockIdx.x * TPB + threadIdx.x;    // one point per thread
    if (t >= N) return;

    float nbl = -beta[0] * LOG2E;              // -beta * log2(e)

    float x0 = x[3 * t + 0];
    float x1 = x[3 * t + 1];
    float x2 = x[3 * t + 2];

    // k-dim Gaussians as (k, k+1) register pairs
    u64 wv[NK / 2];
    float sumw = 0.f;
    #pragma unroll
    for (int k = 0; k < NK; k += 2) {
        float d0 = x2 - sg3[k], d1 = x2 - sg3[k + 1];
        float e0 = ex2f(nbl * d0 * d0), e1 = ex2f(nbl * d1 * d1);
        sumw += e0 + e1;
        wv[k / 2] = pk2(e0, e1);
    }

    // j-dim Gaussians, duplicated pairs
    u64 V[NJ];
    float sumv = 0.f;
    #pragma unroll
    for (int j = 0; j < NJ; ++j) {
        float d = x1 - sg2[j];
        float v = ex2f(nbl * d * d);
        sumv += v;
        V[j] = pk2(v, v);
    }

    float svw = sumv * sumw;

    u64 num = 0ull;
    float sumu = 0.f;

    #pragma unroll 4
    for (int i = 0; i < NI; ++i) {
        float d = x0 - sg1[i];
        float u = ex2f(nbl * d * d);
        sumu += u;
        u64 U = pk2(u, u);

        u64 ta = 0ull;
        const ulonglong2* Wp = reinterpret_cast<const ulonglong2*>(&sW[i * (NJ * NK)]);
        #pragma unroll
        for (int j = 0; j < NJ; ++j) {
            u64 k0 = 0ull, k1 = 0ull;
            #pragma unroll
            for (int q = 0; q < NK / 4; ++q) {        // 5 x LDS.128 broadcast
                ulonglong2 wq = Wp[j * (NK / 4) + q]; // .x=(W,W') .y=(W'',W''')
                k0 = fma2(wq.x, wv[2 * q + 0], k0);
                k1 = fma2(wq.y, wv[2 * q + 1], k1);
            }
            ta = fma2(V[j], add2(k0, k1), ta);
        }
        num = fma2(U, ta, num);
    }

    float nlo, nhi;
    upk2(num, nlo, nhi);
    out[t] = __fdividef(nlo + nhi, sumu * svw);
}

extern "C" void kernel_launch(void* const* d_in, const int* in_sizes, int n_in,
                              void* d_out, int out_size) {
    const float* x       = (const float*)d_in[0];
    const float* centers = (const float*)d_in[1];
    const float* beta    = (const float*)d_in[2];
    const float* lin_w   = (const float*)d_in[3];
    float* out = (float*)d_out;

    int N = in_sizes[0] / 3;                    // 131072
    int nblocks = (N + TPB - 1) / TPB;          // 1024

    rbf_sep_kernel<<<nblocks, TPB>>>(x, centers, beta, lin_w, out, N);
}